// round 4
// baseline (speedup 1.0000x reference)
#include <cuda_runtime.h>
#include <cuda_fp16.h>
#include <cstdint>
#include <cstddef>

// ---------------------------------------------------------------------------
// QLinearLayer: mixed 4/6/8-bit microscaled GEMM, M=8192 N=4096 K=4096, G=32.
// Target is plain sm_100 (no 'a' features!) -> mma.sync + ldmatrix + cp.async.
// Pass 1: dequant all segments to fp16 scratch (row-major [M,K] / [N,K]).
// Pass 2: pipelined fp16 HMMA GEMM, out = A @ B^T + bias (fp32 out).
// ---------------------------------------------------------------------------

static __device__ __half g_Adeq[(size_t)8192 * 4096];  // 64 MB
static __device__ __half g_Bdeq[(size_t)4096 * 4096];  // 32 MB

#define DI static __device__ __forceinline__

DI uint32_t smem_u32(const void* p) {
    uint32_t a;
    asm("{ .reg .u64 t; cvta.to.shared.u64 t, %1; cvt.u32.u64 %0, t; }"
        : "=r"(a) : "l"(p));
    return a;
}
DI void cp_async16(uint32_t smem, const void* gmem) {
    asm volatile("cp.async.cg.shared.global [%0], [%1], 16;"
                 :: "r"(smem), "l"(gmem) : "memory");
}
DI void cp_commit() { asm volatile("cp.async.commit_group;" ::: "memory"); }
template <int N> DI void cp_wait() {
    asm volatile("cp.async.wait_group %0;" :: "n"(N) : "memory");
}
DI void ldsm4(uint32_t* r, uint32_t addr) {
    asm volatile("ldmatrix.sync.aligned.m8n8.x4.shared.b16 {%0,%1,%2,%3}, [%4];"
                 : "=r"(r[0]), "=r"(r[1]), "=r"(r[2]), "=r"(r[3]) : "r"(addr));
}
// b0 = k-half 0 of the n8 group, b1 = k-half 1 of the SAME n8 group.
DI void mma16816(float* d, const uint32_t* a, uint32_t b0, uint32_t b1) {
    asm volatile(
        "mma.sync.aligned.m16n8k16.row.col.f32.f16.f16.f32 "
        "{%0,%1,%2,%3}, {%4,%5,%6,%7}, {%8,%9}, {%0,%1,%2,%3};"
        : "+f"(d[0]), "+f"(d[1]), "+f"(d[2]), "+f"(d[3])
        : "r"(a[0]), "r"(a[1]), "r"(a[2]), "r"(a[3]), "r"(b0), "r"(b1));
}

// ---------------------------------------------------------------------------
// Dequant: int32 quantized + per-group(32) fp32 scale -> fp16 row-major.
// One block per row; 8 elements/thread (4 threads per scale group).
// ---------------------------------------------------------------------------
__global__ void dequant_kernel(const int* __restrict__ Q, const float* __restrict__ SF,
                               __half* __restrict__ dst, int pcols, int col_off,
                               int ldd) {
    int m = blockIdx.y;
    int c = (blockIdx.x * blockDim.x + threadIdx.x) * 8;
    if (c >= pcols) return;
    int gpr = pcols >> 5;
    float s = __ldg(&SF[(size_t)m * gpr + (c >> 5)]);
    const int4* q4 = (const int4*)(Q + (size_t)m * pcols + c);
    int4 q0 = __ldg(q4);
    int4 q1 = __ldg(q4 + 1);
    union { uint4 u; __half2 h2[4]; } pk;
    pk.h2[0] = __floats2half2_rn((float)q0.x * s, (float)q0.y * s);
    pk.h2[1] = __floats2half2_rn((float)q0.z * s, (float)q0.w * s);
    pk.h2[2] = __floats2half2_rn((float)q1.x * s, (float)q1.y * s);
    pk.h2[3] = __floats2half2_rn((float)q1.z * s, (float)q1.w * s);
    *(uint4*)(dst + (size_t)m * ldd + col_off + c) = pk.u;
}

// ---------------------------------------------------------------------------
// GEMM configuration
//   CTA tile 128(M) x 128(N), 8 warps as 2(M) x 4(N) -> warp tile 64 x 32.
//   K-chunk = 32 halves (64B per row), 5-stage cp.async pipeline.
//   SMEM rows padded to 80B: 8 consecutive rows at stride 80 hit 8 distinct
//   16B bank phases (80r mod 128 = {0,80,32,112,64,16,96,48}) -> conflict-free
//   ldmatrix.
// ---------------------------------------------------------------------------
static constexpr int STAGES  = 5;
static constexpr int ROWB    = 80;                 // padded bytes per smem row
static constexpr int TILEB   = 128 * ROWB;         // 10240 per operand tile
static constexpr int STAGE_B = 2 * TILEB;          // 20480
static constexpr int SMEM_SZ = STAGES * STAGE_B;   // 102400
static constexpr int NKCH    = 4096 / 32;          // 128 K chunks

__global__ void __launch_bounds__(256, 2)
mixed_gemm_kernel(const float* __restrict__ bias, float* __restrict__ out) {
    extern __shared__ __align__(128) char smem[];
    const uint32_t sb = smem_u32(smem);
    const int tid  = threadIdx.x;
    const int lane = tid & 31;
    const int w    = tid >> 5;
    const int wm   = w & 1;        // 0..1  (M halves of CTA tile)
    const int wn   = w >> 1;       // 0..3  (N quarters)
    const int mt   = blockIdx.y;   // 64 M tiles
    const int ntb  = blockIdx.x;   // 32 N tiles

    const char* gA = (const char*)g_Adeq + (size_t)mt  * 128 * 8192;
    const char* gB = (const char*)g_Bdeq + (size_t)ntb * 128 * 8192;

    // per-thread cp.async coordinates: 512 16B chunks per operand tile,
    // thread handles chunks {tid, tid+256}: row = ch>>2, col16 = ch&3.
    const int r0 = tid >> 2, c0 = tid & 3;
    const int r1 = (tid + 256) >> 2, c1 = c0;

    auto load_stage = [&](int s, int kc) {
        const uint32_t sA = sb + s * STAGE_B;
        const uint32_t sB = sA + TILEB;
        const size_t  gk = (size_t)kc * 64;
        cp_async16(sA + r0 * ROWB + c0 * 16, gA + (size_t)r0 * 8192 + gk + c0 * 16);
        cp_async16(sA + r1 * ROWB + c1 * 16, gA + (size_t)r1 * 8192 + gk + c1 * 16);
        cp_async16(sB + r0 * ROWB + c0 * 16, gB + (size_t)r0 * 8192 + gk + c0 * 16);
        cp_async16(sB + r1 * ROWB + c1 * 16, gB + (size_t)r1 * 8192 + gk + c1 * 16);
    };

    // prologue
    #pragma unroll
    for (int s = 0; s < STAGES - 1; ++s) { load_stage(s, s); cp_commit(); }

    float acc[4][4][4];
    #pragma unroll
    for (int i = 0; i < 4; ++i)
        #pragma unroll
        for (int j = 0; j < 4; ++j)
            #pragma unroll
            for (int k = 0; k < 4; ++k) acc[i][j][k] = 0.f;

    // ldmatrix per-lane address pieces:
    //   lanes 0-7  -> rows 0-7,  k-bytes 0   (matrix 0)
    //   lanes 8-15 -> rows 8-15, k-bytes 0   (matrix 1)
    //   lanes 16-23-> rows 0-7,  k-bytes 16  (matrix 2)
    //   lanes 24-31-> rows 8-15, k-bytes 16  (matrix 3)
    const int grp   = lane >> 3;
    const int rin16 = (lane & 7) + ((grp & 1) << 3);
    const int kh16  = (grp >> 1) * 16;

    int s = 0;
    for (int kc = 0; kc < NKCH; ++kc) {
        cp_wait<STAGES - 2>();
        __syncthreads();

        // issue the next load before compute (stage consumed S-1 iters ago)
        const int kl = kc + STAGES - 1;
        if (kl < NKCH) load_stage(kl % STAGES, kl);
        cp_commit();

        const uint32_t stA = sb + s * STAGE_B + (wm * 64 + rin16) * ROWB + kh16;
        const uint32_t stB = sb + s * STAGE_B + TILEB + (wn * 32 + rin16) * ROWB + kh16;

        #pragma unroll
        for (int ks = 0; ks < 2; ++ks) {          // two k16 steps per chunk
            uint32_t af[4][4], bf[2][4];
            #pragma unroll
            for (int i = 0; i < 4; ++i)
                ldsm4(af[i], stA + i * 16 * ROWB + ks * 32);
            #pragma unroll
            for (int j = 0; j < 2; ++j)
                ldsm4(bf[j], stB + j * 16 * ROWB + ks * 32);
            // bf[j][0]=(n0-7,k0-7) bf[j][1]=(n8-15,k0-7)
            // bf[j][2]=(n0-7,k8-15) bf[j][3]=(n8-15,k8-15)
            // -> b pair for n0-7 group = {bf[j][0], bf[j][2]},
            //    for n8-15 group       = {bf[j][1], bf[j][3]}.
            #pragma unroll
            for (int i = 0; i < 4; ++i) {
                #pragma unroll
                for (int j = 0; j < 2; ++j) {
                    mma16816(acc[i][2 * j],     af[i], bf[j][0], bf[j][2]);
                    mma16816(acc[i][2 * j + 1], af[i], bf[j][1], bf[j][3]);
                }
            }
        }
        if (++s == STAGES) s = 0;
    }

    // ------------------------- epilogue -------------------------
    const int quad = lane >> 2;
    const int qt   = lane & 3;
    const int mbase = mt * 128 + wm * 64;
    const int nbase = ntb * 128 + wn * 32;

    #pragma unroll
    for (int j = 0; j < 4; ++j) {
        const int col = nbase + j * 8 + qt * 2;
        const float b0 = __ldg(bias + col);
        const float b1 = __ldg(bias + col + 1);
        #pragma unroll
        for (int i = 0; i < 4; ++i) {
            const int row = mbase + i * 16 + quad;
            float2 v0 = { acc[i][j][0] + b0, acc[i][j][1] + b1 };
            float2 v1 = { acc[i][j][2] + b0, acc[i][j][3] + b1 };
            *(float2*)(out + (size_t)row * 4096 + col)       = v0;
            *(float2*)(out + (size_t)(row + 8) * 4096 + col) = v1;
        }
    }
}

// ---------------------------------------------------------------------------
// Launch
// ---------------------------------------------------------------------------
extern "C" void kernel_launch(void* const* d_in, const int* in_sizes, int n_in,
                              void* d_out, int out_size) {
    (void)in_sizes; (void)n_in; (void)out_size;
    const int*   AN   = (const int*)  d_in[0];
    const int*   AS   = (const int*)  d_in[1];
    const int*   AO   = (const int*)  d_in[2];
    const float* SFAN = (const float*)d_in[3];
    const float* SFAS = (const float*)d_in[4];
    const float* SFAO = (const float*)d_in[5];
    const int*   BN   = (const int*)  d_in[6];
    const int*   BS   = (const int*)  d_in[7];
    const int*   BO   = (const int*)  d_in[8];
    const float* SFBN = (const float*)d_in[9];
    const float* SFBS = (const float*)d_in[10];
    const float* SFBO = (const float*)d_in[11];
    const float* bias = (const float*)d_in[12];
    float* out = (float*)d_out;

    __half* Ad;  cudaGetSymbolAddress((void**)&Ad, g_Adeq);
    __half* Bd;  cudaGetSymbolAddress((void**)&Bd, g_Bdeq);

    dequant_kernel<<<dim3(1, 8192), 256>>>(AN, SFAN, Ad, 2048, 0,    4096);
    dequant_kernel<<<dim3(1, 8192), 128>>>(AS, SFAS, Ad, 1024, 2048, 4096);
    dequant_kernel<<<dim3(1, 8192), 128>>>(AO, SFAO, Ad, 1024, 3072, 4096);
    dequant_kernel<<<dim3(1, 4096), 256>>>(BN, SFBN, Bd, 2048, 0,    4096);
    dequant_kernel<<<dim3(1, 4096), 128>>>(BS, SFBS, Bd, 1024, 2048, 4096);
    dequant_kernel<<<dim3(1, 4096), 128>>>(BO, SFBO, Bd, 1024, 3072, 4096);

    cudaFuncSetAttribute(mixed_gemm_kernel,
                         cudaFuncAttributeMaxDynamicSharedMemorySize, SMEM_SZ);
    // grid: x = N tiles (4096/128 = 32), y = M tiles (8192/128 = 64)
    mixed_gemm_kernel<<<dim3(32, 64), 256, SMEM_SZ>>>(bias, out);
}